// round 8
// baseline (speedup 1.0000x reference)
#include <cuda_runtime.h>

#define Bb 32768

#define OFF_KIJ 0
#define OFF_AIK 13107200
#define OFF_TJ  14417920
#define OFF_R   15728640
#define OFF_RT  28835840

static __device__ __forceinline__ int eidx(int i, int j) {
    return i * 9 + j - (j > i ? 1 : 0);
}
static __device__ __forceinline__ float4 f4fma(float a, float4 w, float4 acc) {
    acc.x = fmaf(a, w.x, acc.x);
    acc.y = fmaf(a, w.y, acc.y);
    acc.z = fmaf(a, w.z, acc.z);
    acc.w = fmaf(a, w.w, acc.w);
    return acc;
}
static __device__ __forceinline__ float dot4(float4 a, float4 b) {
    return a.x*b.x + a.y*b.y + a.z*b.z + a.w*b.w;
}
static __device__ __forceinline__ float lrelu(float v) {
    return v >= 0.f ? v : 0.01f * v;
}
// acc += (16-vec y) dot (16x4 slab of W1); W1 quads at base, stride 2 per c
static __device__ __forceinline__ float4 proj16(const float4* __restrict__ Wq, int base,
                                                float4 y0, float4 y1, float4 y2, float4 y3,
                                                float4 acc) {
    acc = f4fma(y0.x, Wq[base + 0],  acc);
    acc = f4fma(y0.y, Wq[base + 2],  acc);
    acc = f4fma(y0.z, Wq[base + 4],  acc);
    acc = f4fma(y0.w, Wq[base + 6],  acc);
    acc = f4fma(y1.x, Wq[base + 8],  acc);
    acc = f4fma(y1.y, Wq[base + 10], acc);
    acc = f4fma(y1.z, Wq[base + 12], acc);
    acc = f4fma(y1.w, Wq[base + 14], acc);
    acc = f4fma(y2.x, Wq[base + 16], acc);
    acc = f4fma(y2.y, Wq[base + 18], acc);
    acc = f4fma(y2.z, Wq[base + 20], acc);
    acc = f4fma(y2.w, Wq[base + 22], acc);
    acc = f4fma(y3.x, Wq[base + 24], acc);
    acc = f4fma(y3.y, Wq[base + 26], acc);
    acc = f4fma(y3.z, Wq[base + 28], acc);
    acc = f4fma(y3.w, Wq[base + 30], acc);
    return acc;
}

__global__ __launch_bounds__(128, 8) void gnn_kernel(
    const float* __restrict__ x,
    const float* __restrict__ ew,
    const float* __restrict__ eigen,
    const float* __restrict__ a0p,
    const float* __restrict__ W0,
    const float* __restrict__ b0,
    const float* __restrict__ W1,
    const float* __restrict__ b1,
    const float* __restrict__ bp,
    const float* __restrict__ cp,
    const float* __restrict__ ww,
    float* __restrict__ out)
{
    const int b    = blockIdx.x;
    const int tid  = threadIdx.x;
    const int k    = tid >> 5;     // warp id == K group
    const int lane = tid & 31;

    __shared__ __align__(8)  float s_w[4][90];
    __shared__ float s_dinv[4][10];
    __shared__ float s_A[4][10][10];
    __shared__ __align__(16) float s_x[4][4][10][4];   // [k][hop][j][c(pad4)]
    __shared__ __align__(16) float s_Y1[4][10][20];    // 16 used, pad 20
    __shared__ __align__(16) float s_z[4][2][10][12];  // Horner ping-pong, 8 used pad 12
    __shared__ __align__(16) float s_y[4][10][8];
    __shared__ __align__(16) float s_yw[4][10][8];
    __shared__ float s_pm[4][10];
    __shared__ float s_tk[4][10];
    __shared__ __align__(16) float s_W0[192];   // [hop][3][16]
    __shared__ __align__(16) float s_W1[512];   // [hop][16][8]
    __shared__ __align__(16) float s_b0[16];
    __shared__ __align__(16) float s_b1[8];
    __shared__ __align__(16) float s_bp[8];
    __shared__ __align__(16) float s_cp[8];
    __shared__ __align__(16) float s_ww[64];
    __shared__ float s_a0;

    // ---- block-coop parameter staging (vectorized) ----
    if (tid < 48) reinterpret_cast<float4*>(s_W0)[tid] =
        reinterpret_cast<const float4*>(W0)[tid];
    reinterpret_cast<float4*>(s_W1)[tid] =
        reinterpret_cast<const float4*>(W1)[tid];
    if (tid < 16)       s_b0[tid]      = b0[tid];
    else if (tid < 24)  s_b1[tid - 16] = b1[tid - 16];
    else if (tid < 32)  s_bp[tid - 24] = bp[tid - 24];
    else if (tid < 40)  s_cp[tid - 32] = cp[tid - 32];
    else if (tid == 40) s_a0           = a0p[0];
    if (tid >= 64) s_ww[tid - 64] = ww[tid - 64];

    // ---- per-warp staging: this warp's K group ----
    const float eig = eigen[(size_t)k * Bb + b];   // warp-uniform

    {
        const float2* ewb2 = reinterpret_cast<const float2*>(ew + (size_t)b * 90)
                           + (size_t)k * (Bb * 45);
        float2* sw2 = reinterpret_cast<float2*>(s_w[k]);
        sw2[lane] = ewb2[lane];
        if (lane < 13) sw2[lane + 32] = ewb2[lane + 32];
    }
    {
        const float2* xb2 = reinterpret_cast<const float2*>(x + (size_t)b * 30)
                          + (size_t)k * (Bb * 15);
        if (lane < 15) {
            float2 v = xb2[lane];
            int r0 = 2 * lane, r1 = r0 + 1;
            int j0 = r0 / 3, c0 = r0 % 3;
            int j1 = r1 / 3, c1 = r1 % 3;
            s_x[k][0][j0][c0] = v.x;
            s_x[k][0][j1][c1] = v.y;
            if (c0 == 2) s_pm[k][j0] = fmaxf(v.x, 0.0f);
            if (c1 == 2) s_pm[k][j1] = fmaxf(v.y, 0.0f);
        }
    }
    __syncwarp();

    // ---- degree + dinv (lane<10) ----
    if (lane < 10) {
        float d = 0.f;
        #pragma unroll
        for (int i = 0; i < 10; i++)
            if (i != lane) d += s_w[k][eidx(i, lane)];
        s_dinv[k][lane] = (d > 0.f) ? rsqrtf(d) : 0.f;
    }
    __syncwarp();

    // ---- adjacency + R/R_t (lane<25, quad of elements each, STG.128) ----
    if (lane < 25) {
        const int r = lane * 4;
        float4 vR, vRT;
        float aq[4];
        #pragma unroll
        for (int t = 0; t < 4; t++) {
            int rr = r + t;
            int n = rr / 10, m = rr % 10;
            bool diag = (n == m);
            float wnm = diag ? 0.f : s_w[k][eidx(n, m)];
            float wmn = diag ? 0.f : s_w[k][eidx(m, n)];
            aq[t] = wnm * s_dinv[k][n] * s_dinv[k][m];
            (&vR.x)[t]  = wnm * eig;
            (&vRT.x)[t] = wmn * eig;
            s_A[k][n][m] = aq[t];
        }
        float* dR  = out + OFF_R  + (size_t)k * (Bb * 100) + (size_t)b * 100 + r;
        float* dRT = out + OFF_RT + (size_t)k * (Bb * 100) + (size_t)b * 100 + r;
        *reinterpret_cast<float4*>(dR)  = vR;
        *reinterpret_cast<float4*>(dRT) = vRT;
    }
    __syncwarp();

    // barrier 1: W0/W1/biases visible to all warps (also covers everything above)
    __syncthreads();

    // ================= layer-1 hop propagation (lane<30: j1, c1) =================
    const int j1 = lane / 3;
    const int c1 = lane - 3 * j1;
    float acol1[10];
    if (lane < 30) {
        #pragma unroll
        for (int i = 0; i < 10; i++) acol1[i] = s_A[k][i][j1];
    }
    #pragma unroll
    for (int hk = 0; hk < 3; hk++) {
        if (lane < 30) {
            const float* src = &s_x[k][hk][0][c1];
            float s = 0.f;
            #pragma unroll
            for (int i = 0; i < 10; i++) s = fmaf(acol1[i], src[i * 4], s);
            s_x[k][hk + 1][j1][c1] = s;
        }
        __syncwarp();
    }

    // ---- warp-local 20-lane mapping: (j2, h2) ----
    const int j2 = lane >> 1;
    const int h2 = lane & 1;
    const bool act = (lane < 20);

    // ================= layer-1 projection =================
    if (act) {
        const float4* W0q = reinterpret_cast<const float4*>(s_W0);
        float4 acc0 = make_float4(0.f, 0.f, 0.f, 0.f);
        float4 acc1 = make_float4(0.f, 0.f, 0.f, 0.f);
        #pragma unroll
        for (int hop = 0; hop < 4; hop++) {
            float4 xv = *reinterpret_cast<const float4*>(s_x[k][hop][j2]);
            int base = hop * 12 + h2 * 2;
            acc0 = f4fma(xv.x, W0q[base + 0], acc0);
            acc1 = f4fma(xv.x, W0q[base + 1], acc1);
            acc0 = f4fma(xv.y, W0q[base + 4], acc0);
            acc1 = f4fma(xv.y, W0q[base + 5], acc1);
            acc0 = f4fma(xv.z, W0q[base + 8], acc0);
            acc1 = f4fma(xv.z, W0q[base + 9], acc1);
        }
        float4 bb0 = reinterpret_cast<const float4*>(s_b0)[h2 * 2];
        float4 bb1 = reinterpret_cast<const float4*>(s_b0)[h2 * 2 + 1];
        float4 v0 = make_float4(lrelu(acc0.x + bb0.x), lrelu(acc0.y + bb0.y),
                                lrelu(acc0.z + bb0.z), lrelu(acc0.w + bb0.w));
        float4 v1 = make_float4(lrelu(acc1.x + bb1.x), lrelu(acc1.y + bb1.y),
                                lrelu(acc1.z + bb1.z), lrelu(acc1.w + bb1.w));
        float* yr = &s_Y1[k][j2][h2 * 8];
        reinterpret_cast<float4*>(yr)[0] = v0;
        reinterpret_cast<float4*>(yr)[1] = v1;
    }
    __syncwarp();

    // ================= layer-2, Horner form (warp-local) =================
    const float4* W1q = reinterpret_cast<const float4*>(s_W1);
    float acol2[10];
    float4 y0, y1, y2, y3;
    if (act) {
        #pragma unroll
        for (int i = 0; i < 10; i++) acol2[i] = s_A[k][i][j2];
        const float4* yq = reinterpret_cast<const float4*>(s_Y1[k][j2]);
        y0 = yq[0]; y1 = yq[1]; y2 = yq[2]; y3 = yq[3];
        float4 acc = make_float4(0.f, 0.f, 0.f, 0.f);
        acc = proj16(W1q, 3 * 32 + h2, y0, y1, y2, y3, acc);
        *reinterpret_cast<float4*>(&s_z[k][0][j2][h2 * 4]) = acc;
    }
    __syncwarp();

    int cur = 0;
    #pragma unroll
    for (int hop = 2; hop >= 1; hop--) {
        if (act) {
            float4 agg = make_float4(0.f, 0.f, 0.f, 0.f);
            const float* zp = &s_z[k][cur][0][h2 * 4];
            #pragma unroll
            for (int i = 0; i < 10; i++) {
                float4 zv = *reinterpret_cast<const float4*>(&zp[i * 12]);
                agg = f4fma(acol2[i], zv, agg);
            }
            agg = proj16(W1q, hop * 32 + h2, y0, y1, y2, y3, agg);
            *reinterpret_cast<float4*>(&s_z[k][cur ^ 1][j2][h2 * 4]) = agg;
        }
        __syncwarp();
        cur ^= 1;
    }
    if (act) {
        float4 agg = make_float4(0.f, 0.f, 0.f, 0.f);
        const float* zp = &s_z[k][cur][0][h2 * 4];
        #pragma unroll
        for (int i = 0; i < 10; i++) {
            float4 zv = *reinterpret_cast<const float4*>(&zp[i * 12]);
            agg = f4fma(acol2[i], zv, agg);
        }
        agg = proj16(W1q, 0 * 32 + h2, y0, y1, y2, y3, agg);
        float4 bb = reinterpret_cast<const float4*>(s_b1)[h2];
        float4 v = make_float4(lrelu(agg.x + bb.x), lrelu(agg.y + bb.y),
                               lrelu(agg.z + bb.z), lrelu(agg.w + bb.w));
        reinterpret_cast<float4*>(s_y[k][j2])[h2] = v;
    }
    __syncwarp();

    // ================= per-warp epilogue =================
    if (act) {
        const float4* yv = reinterpret_cast<const float4*>(s_y[k][j2]);
        float4 ya = yv[0], yb = yv[1];
        const float4* wwv = reinterpret_cast<const float4*>(s_ww);
        int d = h2 * 4;
        float4 r;
        r.x = dot4(ya, wwv[(d + 0) * 2]) + dot4(yb, wwv[(d + 0) * 2 + 1]);
        r.y = dot4(ya, wwv[(d + 1) * 2]) + dot4(yb, wwv[(d + 1) * 2 + 1]);
        r.z = dot4(ya, wwv[(d + 2) * 2]) + dot4(yb, wwv[(d + 2) * 2 + 1]);
        r.w = dot4(ya, wwv[(d + 3) * 2]) + dot4(yb, wwv[(d + 3) * 2 + 1]);
        reinterpret_cast<float4*>(s_yw[k][j2])[h2] = r;
    }
    // a_ik, t_k (lane<10)
    if (lane < 10) {
        const float4* yv = reinterpret_cast<const float4*>(s_y[k][lane]);
        float4 ya = yv[0], yb = yv[1];
        const float4* bpv = reinterpret_cast<const float4*>(s_bp);
        const float4* cpv = reinterpret_cast<const float4*>(s_cp);
        float ay = dot4(ya, bpv[0]) + dot4(yb, bpv[1]);
        float ty = dot4(ya, cpv[0]) + dot4(yb, cpv[1]);
        out[OFF_AIK + (size_t)k * (Bb * 10) + (size_t)b * 10 + lane] = s_a0 + fmaxf(ay, 0.f);
        float tk = ty * (1.0f - s_pm[k][lane]);
        if (tk == 0.0f) tk = -10000000000.0f;
        s_tk[k][lane] = tk;
    }

    // barrier 2: cross-K coupling starts here
    __syncthreads();

    // t_j = softmax over K
    if (tid < 10) {
        float t0 = s_tk[0][tid], t1 = s_tk[1][tid], t2 = s_tk[2][tid], t3 = s_tk[3][tid];
        float m = fmaxf(fmaxf(t0, t1), fmaxf(t2, t3));
        float e0 = __expf(t0 - m), e1 = __expf(t1 - m);
        float e2 = __expf(t2 - m), e3 = __expf(t3 - m);
        float inv = 1.f / (e0 + e1 + e2 + e3);
        float* pt = out + OFF_TJ + (size_t)b * 10 + tid;
        pt[0]            = e0 * inv;
        pt[Bb * 10]      = e1 * inv;
        pt[2 * Bb * 10]  = e2 * inv;
        pt[3 * Bb * 10]  = e3 * inv;
    }

    // K_y + softmax over K -> k_ij
    if (tid < 100) {
        int n = tid / 10, m = tid % 10;
        float kv[4];
        #pragma unroll
        for (int kk = 0; kk < 4; kk++) {
            const float4* av = reinterpret_cast<const float4*>(s_yw[kk][n]);
            const float4* cv = reinterpret_cast<const float4*>(s_y[kk][m]);
            kv[kk] = dot4(av[0], cv[0]) + dot4(av[1], cv[1]);
        }
        float mx = fmaxf(fmaxf(kv[0], kv[1]), fmaxf(kv[2], kv[3]));
        float e[4];
        float ssum = 0.f;
        #pragma unroll
        for (int kk = 0; kk < 4; kk++) { e[kk] = __expf(kv[kk] - mx); ssum += e[kk]; }
        float inv = 1.f / ssum;
        float* pk = out + OFF_KIJ + (size_t)b * 100 + tid;
        #pragma unroll
        for (int kk = 0; kk < 4; kk++)
            pk[(size_t)kk * (Bb * 100)] = e[kk] * inv;
    }
}

extern "C" void kernel_launch(void* const* d_in, const int* in_sizes, int n_in,
                              void* d_out, int out_size) {
    (void)out_size;
    const float* x  = (const float*)d_in[0];
    const float* ew = (const float*)d_in[2];
    int base = 3;
    if (n_in >= 15 && in_sizes[3] == 1 && in_sizes[4] == 1 && in_sizes[5] == 1) base = 6;
    const float* eigen = (const float*)d_in[base + 0];
    const float* a0    = (const float*)d_in[base + 1];
    const float* W0    = (const float*)d_in[base + 2];
    const float* b0    = (const float*)d_in[base + 3];
    const float* W1    = (const float*)d_in[base + 4];
    const float* b1    = (const float*)d_in[base + 5];
    const float* bp    = (const float*)d_in[base + 6];
    const float* cp    = (const float*)d_in[base + 7];
    const float* ww    = (const float*)d_in[base + 8];

    gnn_kernel<<<Bb, 128>>>(x, ew, eigen, a0, W0, b0, W1, b1, bp, cp, ww, (float*)d_out);
}

// round 9
// speedup vs baseline: 1.1604x; 1.1604x over previous
#include <cuda_runtime.h>

#define Bb 32768

#define OFF_KIJ 0
#define OFF_AIK 13107200
#define OFF_TJ  14417920
#define OFF_R   15728640
#define OFF_RT  28835840

static __device__ __forceinline__ int eidx(int i, int j) {
    return i * 9 + j - (j > i ? 1 : 0);
}
static __device__ __forceinline__ float4 f4fma(float a, float4 w, float4 acc) {
    acc.x = fmaf(a, w.x, acc.x);
    acc.y = fmaf(a, w.y, acc.y);
    acc.z = fmaf(a, w.z, acc.z);
    acc.w = fmaf(a, w.w, acc.w);
    return acc;
}
static __device__ __forceinline__ float dot4(float4 a, float4 b) {
    return a.x*b.x + a.y*b.y + a.z*b.z + a.w*b.w;
}
static __device__ __forceinline__ float lrelu(float v) {
    return v >= 0.f ? v : 0.01f * v;
}
static __device__ __forceinline__ float4 proj16(const float4* __restrict__ Wq, int base,
                                                float4 y0, float4 y1, float4 y2, float4 y3,
                                                float4 acc) {
    acc = f4fma(y0.x, Wq[base + 0],  acc);
    acc = f4fma(y0.y, Wq[base + 2],  acc);
    acc = f4fma(y0.z, Wq[base + 4],  acc);
    acc = f4fma(y0.w, Wq[base + 6],  acc);
    acc = f4fma(y1.x, Wq[base + 8],  acc);
    acc = f4fma(y1.y, Wq[base + 10], acc);
    acc = f4fma(y1.z, Wq[base + 12], acc);
    acc = f4fma(y1.w, Wq[base + 14], acc);
    acc = f4fma(y2.x, Wq[base + 16], acc);
    acc = f4fma(y2.y, Wq[base + 18], acc);
    acc = f4fma(y2.z, Wq[base + 20], acc);
    acc = f4fma(y2.w, Wq[base + 22], acc);
    acc = f4fma(y3.x, Wq[base + 24], acc);
    acc = f4fma(y3.y, Wq[base + 26], acc);
    acc = f4fma(y3.z, Wq[base + 28], acc);
    acc = f4fma(y3.w, Wq[base + 30], acc);
    return acc;
}

__global__ __launch_bounds__(128, 8) void gnn_kernel(
    const float* __restrict__ x,
    const float* __restrict__ ew,
    const float* __restrict__ eigen,
    const float* __restrict__ a0p,
    const float* __restrict__ W0,
    const float* __restrict__ b0,
    const float* __restrict__ W1,
    const float* __restrict__ b1,
    const float* __restrict__ bp,
    const float* __restrict__ cp,
    const float* __restrict__ ww,
    float* __restrict__ out)
{
    const int b    = blockIdx.x;
    const int tid  = threadIdx.x;
    const int k    = tid >> 5;     // warp id == K group (per-warp phases)
    const int lane = tid & 31;

    __shared__ __align__(8)  float s_w[4][90];
    __shared__ float s_dinv[4][10];
    __shared__ float s_A[4][10][11];                  // padded row 11
    __shared__ __align__(16) float s_x[4][4][10][4];  // [k][hop][j][c(pad4)]
    __shared__ __align__(16) float s_Y1[4][10][20];   // 16 used, pad 20
    __shared__ __align__(16) float s_z[2][4][10][12]; // ping-pong Horner, 8 used pad 12
    __shared__ __align__(16) float s_y[4][10][8];
    __shared__ __align__(16) float s_yw[4][10][8];
    __shared__ float s_pm[4][10];
    __shared__ float s_tk[4][10];
    __shared__ __align__(16) float s_W0[192];   // [hop][3][16]
    __shared__ __align__(16) float s_W1[512];   // [hop][16][8]
    __shared__ __align__(16) float s_b0[16];
    __shared__ __align__(16) float s_b1[8];
    __shared__ __align__(16) float s_bp[8];
    __shared__ __align__(16) float s_cp[8];
    __shared__ __align__(16) float s_ww[64];
    __shared__ float s_a0;

    // ---- block-coop parameter staging (vectorized) ----
    if (tid < 48) reinterpret_cast<float4*>(s_W0)[tid] =
        reinterpret_cast<const float4*>(W0)[tid];
    reinterpret_cast<float4*>(s_W1)[tid] =
        reinterpret_cast<const float4*>(W1)[tid];
    if (tid < 64) s_ww[tid] = ww[tid];
    if (tid < 16)       s_b0[tid]      = b0[tid];
    else if (tid < 24)  s_b1[tid - 16] = b1[tid - 16];
    else if (tid < 32)  s_bp[tid - 24] = bp[tid - 24];
    else if (tid < 40)  s_cp[tid - 32] = cp[tid - 32];
    else if (tid == 40) s_a0           = a0p[0];

    // ---- per-warp staging: this warp's K group ----
    const float eig = eigen[(size_t)k * Bb + b];   // warp-uniform

    {
        const float2* ewb2 = reinterpret_cast<const float2*>(ew + (size_t)b * 90)
                           + (size_t)k * (Bb * 45);
        float2* sw2 = reinterpret_cast<float2*>(s_w[k]);
        sw2[lane] = ewb2[lane];
        if (lane < 13) sw2[lane + 32] = ewb2[lane + 32];
    }
    {
        const float2* xb2 = reinterpret_cast<const float2*>(x + (size_t)b * 30)
                          + (size_t)k * (Bb * 15);
        if (lane < 15) {
            float2 v = xb2[lane];
            int r0 = 2 * lane, r1 = r0 + 1;
            int j0 = r0 / 3, c0 = r0 % 3;
            int j1 = r1 / 3, c1 = r1 % 3;
            s_x[k][0][j0][c0] = v.x;
            s_x[k][0][j1][c1] = v.y;
            if (c0 == 2) s_pm[k][j0] = fmaxf(v.x, 0.0f);
            if (c1 == 2) s_pm[k][j1] = fmaxf(v.y, 0.0f);
        }
    }
    __syncwarp();

    // ---- degree + dinv (per-warp, lane<10) ----
    if (lane < 10) {
        float d = 0.f;
        #pragma unroll
        for (int i = 0; i < 10; i++)
            if (i != lane) d += s_w[k][eidx(i, lane)];
        s_dinv[k][lane] = (d > 0.f) ? rsqrtf(d) : 0.f;
    }
    __syncwarp();

    // ---- adjacency + R/R_t (per-warp, lane<25, STG.128) ----
    if (lane < 25) {
        const int r = lane * 4;
        float4 vR, vRT;
        #pragma unroll
        for (int t = 0; t < 4; t++) {
            int rr = r + t;
            int n = rr / 10, m = rr % 10;
            bool diag = (n == m);
            float wnm = diag ? 0.f : s_w[k][eidx(n, m)];
            float wmn = diag ? 0.f : s_w[k][eidx(m, n)];
            s_A[k][n][m] = wnm * s_dinv[k][n] * s_dinv[k][m];
            (&vR.x)[t]  = wnm * eig;
            (&vRT.x)[t] = wmn * eig;
        }
        float* dR  = out + OFF_R  + (size_t)k * (Bb * 100) + (size_t)b * 100 + r;
        float* dRT = out + OFF_RT + (size_t)k * (Bb * 100) + (size_t)b * 100 + r;
        *reinterpret_cast<float4*>(dR)  = vR;
        *reinterpret_cast<float4*>(dRT) = vRT;
    }
    __syncwarp();

    // ---- layer-1 hop propagation (per-warp, lane<30: j1, c1) ----
    const int j1 = lane / 3;
    const int c1 = lane - 3 * j1;
    float acol1[10];
    if (lane < 30) {
        #pragma unroll
        for (int i = 0; i < 10; i++) acol1[i] = s_A[k][i][j1];
    }
    #pragma unroll
    for (int hk = 0; hk < 3; hk++) {
        if (lane < 30) {
            const float* src = &s_x[k][hk][0][c1];
            float s = 0.f;
            #pragma unroll
            for (int i = 0; i < 10; i++) s = fmaf(acol1[i], src[i * 4], s);
            s_x[k][hk + 1][j1][c1] = s;
        }
        __syncwarp();
    }

    // barrier 1: cross-warp from here (packed mappings read all k slices)
    __syncthreads();

    // ---- packed 80-thread mapping: (k2, j2, h2) ----
    const int k2 = tid / 20;
    const int r2 = tid % 20;
    const int j2 = r2 >> 1;
    const int h2 = r2 & 1;
    const bool act = (tid < 80);

    // ================= layer-1 projection =================
    if (act) {
        const float4* W0q = reinterpret_cast<const float4*>(s_W0);
        float4 acc0 = make_float4(0.f, 0.f, 0.f, 0.f);
        float4 acc1 = make_float4(0.f, 0.f, 0.f, 0.f);
        #pragma unroll
        for (int hop = 0; hop < 4; hop++) {
            float4 xv = *reinterpret_cast<const float4*>(s_x[k2][hop][j2]);
            int base = hop * 12 + h2 * 2;
            acc0 = f4fma(xv.x, W0q[base + 0], acc0);
            acc1 = f4fma(xv.x, W0q[base + 1], acc1);
            acc0 = f4fma(xv.y, W0q[base + 4], acc0);
            acc1 = f4fma(xv.y, W0q[base + 5], acc1);
            acc0 = f4fma(xv.z, W0q[base + 8], acc0);
            acc1 = f4fma(xv.z, W0q[base + 9], acc1);
        }
        float4 bb0 = reinterpret_cast<const float4*>(s_b0)[h2 * 2];
        float4 bb1 = reinterpret_cast<const float4*>(s_b0)[h2 * 2 + 1];
        float4 v0 = make_float4(lrelu(acc0.x + bb0.x), lrelu(acc0.y + bb0.y),
                                lrelu(acc0.z + bb0.z), lrelu(acc0.w + bb0.w));
        float4 v1 = make_float4(lrelu(acc1.x + bb1.x), lrelu(acc1.y + bb1.y),
                                lrelu(acc1.z + bb1.z), lrelu(acc1.w + bb1.w));
        float* yr = &s_Y1[k2][j2][h2 * 8];
        reinterpret_cast<float4*>(yr)[0] = v0;
        reinterpret_cast<float4*>(yr)[1] = v1;
    }
    __syncwarp();   // Y1 row halves come from adjacent lanes only

    // ================= layer-2, Horner form (packed) =================
    const float4* W1q = reinterpret_cast<const float4*>(s_W1);
    float acol2[10];
    float4 y0, y1, y2, y3;
    if (act) {
        #pragma unroll
        for (int i = 0; i < 10; i++) acol2[i] = s_A[k2][i][j2];
        const float4* yq = reinterpret_cast<const float4*>(s_Y1[k2][j2]);
        y0 = yq[0]; y1 = yq[1]; y2 = yq[2]; y3 = yq[3];
        float4 acc = make_float4(0.f, 0.f, 0.f, 0.f);
        acc = proj16(W1q, 3 * 32 + h2, y0, y1, y2, y3, acc);
        *reinterpret_cast<float4*>(&s_z[0][k2][j2][h2 * 4]) = acc;
    }
    __syncthreads();   // barrier 2 (z spans warp boundaries for k2=1,3)

    int cur = 0;
    #pragma unroll
    for (int hop = 2; hop >= 1; hop--) {
        if (act) {
            float4 agg = make_float4(0.f, 0.f, 0.f, 0.f);
            const float* zp = &s_z[cur][k2][0][h2 * 4];
            #pragma unroll
            for (int i = 0; i < 10; i++) {
                float4 zv = *reinterpret_cast<const float4*>(&zp[i * 12]);
                agg = f4fma(acol2[i], zv, agg);
            }
            agg = proj16(W1q, hop * 32 + h2, y0, y1, y2, y3, agg);
            *reinterpret_cast<float4*>(&s_z[cur ^ 1][k2][j2][h2 * 4]) = agg;
        }
        __syncthreads();   // barriers 3,4
        cur ^= 1;
    }
    if (act) {
        float4 agg = make_float4(0.f, 0.f, 0.f, 0.f);
        const float* zp = &s_z[cur][k2][0][h2 * 4];
        #pragma unroll
        for (int i = 0; i < 10; i++) {
            float4 zv = *reinterpret_cast<const float4*>(&zp[i * 12]);
            agg = f4fma(acol2[i], zv, agg);
        }
        agg = proj16(W1q, 0 * 32 + h2, y0, y1, y2, y3, agg);
        float4 bb = reinterpret_cast<const float4*>(s_b1)[h2];
        float4 v = make_float4(lrelu(agg.x + bb.x), lrelu(agg.y + bb.y),
                               lrelu(agg.z + bb.z), lrelu(agg.w + bb.w));
        reinterpret_cast<float4*>(s_y[k2][j2])[h2] = v;
    }
    __syncthreads();   // barrier 5 (a_ik reads cross-warp s_y)

    // ================= epilogue =================
    if (act) {
        const float4* yv = reinterpret_cast<const float4*>(s_y[k2][j2]);
        float4 ya = yv[0], yb = yv[1];
        const float4* wwv = reinterpret_cast<const float4*>(s_ww);
        int d = h2 * 4;
        float4 r;
        r.x = dot4(ya, wwv[(d + 0) * 2]) + dot4(yb, wwv[(d + 0) * 2 + 1]);
        r.y = dot4(ya, wwv[(d + 1) * 2]) + dot4(yb, wwv[(d + 1) * 2 + 1]);
        r.z = dot4(ya, wwv[(d + 2) * 2]) + dot4(yb, wwv[(d + 2) * 2 + 1]);
        r.w = dot4(ya, wwv[(d + 3) * 2]) + dot4(yb, wwv[(d + 3) * 2 + 1]);
        reinterpret_cast<float4*>(s_yw[k2][j2])[h2] = r;
    }
    if (tid < 40) {
        int kk = tid / 10, j = tid % 10;
        const float4* yv = reinterpret_cast<const float4*>(s_y[kk][j]);
        float4 ya = yv[0], yb = yv[1];
        const float4* bpv = reinterpret_cast<const float4*>(s_bp);
        const float4* cpv = reinterpret_cast<const float4*>(s_cp);
        float ay = dot4(ya, bpv[0]) + dot4(yb, bpv[1]);
        float ty = dot4(ya, cpv[0]) + dot4(yb, cpv[1]);
        out[OFF_AIK + (size_t)kk * (Bb * 10) + (size_t)b * 10 + j] = s_a0 + fmaxf(ay, 0.f);
        float tk = ty * (1.0f - s_pm[kk][j]);
        if (tk == 0.0f) tk = -10000000000.0f;
        s_tk[kk][j] = tk;
    }
    __syncthreads();   // barrier 6

    // t_j = softmax over K
    if (tid < 10) {
        float t0 = s_tk[0][tid], t1 = s_tk[1][tid], t2 = s_tk[2][tid], t3 = s_tk[3][tid];
        float m = fmaxf(fmaxf(t0, t1), fmaxf(t2, t3));
        float e0 = __expf(t0 - m), e1 = __expf(t1 - m);
        float e2 = __expf(t2 - m), e3 = __expf(t3 - m);
        float inv = 1.f / (e0 + e1 + e2 + e3);
        float* pt = out + OFF_TJ + (size_t)b * 10 + tid;
        pt[0]            = e0 * inv;
        pt[Bb * 10]      = e1 * inv;
        pt[2 * Bb * 10]  = e2 * inv;
        pt[3 * Bb * 10]  = e3 * inv;
    }

    // K_y + softmax over K -> k_ij
    if (tid < 100) {
        int n = tid / 10, m = tid % 10;
        float kv[4];
        #pragma unroll
        for (int kk = 0; kk < 4; kk++) {
            const float4* av = reinterpret_cast<const float4*>(s_yw[kk][n]);
            const float4* cv = reinterpret_cast<const float4*>(s_y[kk][m]);
            kv[kk] = dot4(av[0], cv[0]) + dot4(av[1], cv[1]);
        }
        float mx = fmaxf(fmaxf(kv[0], kv[1]), fmaxf(kv[2], kv[3]));
        float e[4];
        float ssum = 0.f;
        #pragma unroll
        for (int kk = 0; kk < 4; kk++) { e[kk] = __expf(kv[kk] - mx); ssum += e[kk]; }
        float inv = 1.f / ssum;
        float* pk = out + OFF_KIJ + (size_t)b * 100 + tid;
        #pragma unroll
        for (int kk = 0; kk < 4; kk++)
            pk[(size_t)kk * (Bb * 100)] = e[kk] * inv;
    }
}

extern "C" void kernel_launch(void* const* d_in, const int* in_sizes, int n_in,
                              void* d_out, int out_size) {
    (void)out_size;
    const float* x  = (const float*)d_in[0];
    const float* ew = (const float*)d_in[2];
    int base = 3;
    if (n_in >= 15 && in_sizes[3] == 1 && in_sizes[4] == 1 && in_sizes[5] == 1) base = 6;
    const float* eigen = (const float*)d_in[base + 0];
    const float* a0    = (const float*)d_in[base + 1];
    const float* W0    = (const float*)d_in[base + 2];
    const float* b0    = (const float*)d_in[base + 3];
    const float* W1    = (const float*)d_in[base + 4];
    const float* b1    = (const float*)d_in[base + 5];
    const float* bp    = (const float*)d_in[base + 6];
    const float* cp    = (const float*)d_in[base + 7];
    const float* ww    = (const float*)d_in[base + 8];

    gnn_kernel<<<Bb, 128>>>(x, ew, eigen, a0, W0, b0, W1, b1, bp, cp, ww, (float*)d_out);
}

// round 10
// speedup vs baseline: 1.2488x; 1.0762x over previous
#include <cuda_runtime.h>

#define Bb 32768

#define OFF_KIJ 0
#define OFF_AIK 13107200
#define OFF_TJ  14417920
#define OFF_R   15728640
#define OFF_RT  28835840

static __device__ __forceinline__ int eidx(int i, int j) {
    return i * 9 + j - (j > i ? 1 : 0);
}
static __device__ __forceinline__ float4 f4fma(float a, float4 w, float4 acc) {
    acc.x = fmaf(a, w.x, acc.x);
    acc.y = fmaf(a, w.y, acc.y);
    acc.z = fmaf(a, w.z, acc.z);
    acc.w = fmaf(a, w.w, acc.w);
    return acc;
}
static __device__ __forceinline__ float dot4(float4 a, float4 b) {
    return a.x*b.x + a.y*b.y + a.z*b.z + a.w*b.w;
}
static __device__ __forceinline__ float lrelu(float v) {
    return v >= 0.f ? v : 0.01f * v;
}
static __device__ __forceinline__ float4 proj16(const float4* __restrict__ Wq, int base,
                                                float4 y0, float4 y1, float4 y2, float4 y3,
                                                float4 acc) {
    acc = f4fma(y0.x, Wq[base + 0],  acc);
    acc = f4fma(y0.y, Wq[base + 2],  acc);
    acc = f4fma(y0.z, Wq[base + 4],  acc);
    acc = f4fma(y0.w, Wq[base + 6],  acc);
    acc = f4fma(y1.x, Wq[base + 8],  acc);
    acc = f4fma(y1.y, Wq[base + 10], acc);
    acc = f4fma(y1.z, Wq[base + 12], acc);
    acc = f4fma(y1.w, Wq[base + 14], acc);
    acc = f4fma(y2.x, Wq[base + 16], acc);
    acc = f4fma(y2.y, Wq[base + 18], acc);
    acc = f4fma(y2.z, Wq[base + 20], acc);
    acc = f4fma(y2.w, Wq[base + 22], acc);
    acc = f4fma(y3.x, Wq[base + 24], acc);
    acc = f4fma(y3.y, Wq[base + 26], acc);
    acc = f4fma(y3.z, Wq[base + 28], acc);
    acc = f4fma(y3.w, Wq[base + 30], acc);
    return acc;
}

__global__ __launch_bounds__(128, 8) void gnn_kernel(
    const float* __restrict__ x,
    const float* __restrict__ ew,
    const float* __restrict__ eigen,
    const float* __restrict__ a0p,
    const float* __restrict__ W0,
    const float* __restrict__ b0,
    const float* __restrict__ W1,
    const float* __restrict__ b1,
    const float* __restrict__ bp,
    const float* __restrict__ cp,
    const float* __restrict__ ww,
    float* __restrict__ out)
{
    const int b    = blockIdx.x;
    const int tid  = threadIdx.x;
    const int k    = tid >> 5;     // warp id == K group (per-warp phases)
    const int lane = tid & 31;

    __shared__ __align__(8)  float s_w[4][90];
    __shared__ float s_dinv[4][10];
    __shared__ float s_A[4][10][11];                  // padded row 11
    __shared__ __align__(16) float s_x[4][4][10][4];  // [k][hop][j][c(pad4)]
    __shared__ __align__(16) float s_Y1[4][10][20];   // 16 used, pad 20
    __shared__ __align__(16) float s_z[2][4][10][12]; // ping-pong Horner
    __shared__ __align__(16) float s_y[4][10][8];
    __shared__ __align__(16) float s_yw[4][10][8];
    __shared__ float s_K[4][10][10];                  // K_y staging
    __shared__ float s_pm[4][10];
    __shared__ float s_tk[4][10];
    __shared__ __align__(16) float s_W0[192];   // [hop][3][16]
    __shared__ __align__(16) float s_W1[512];   // [hop][16][8]
    __shared__ __align__(16) float s_b0[16];
    __shared__ __align__(16) float s_b1[8];
    __shared__ __align__(16) float s_bp[8];
    __shared__ __align__(16) float s_cp[8];
    __shared__ __align__(16) float s_ww[64];
    __shared__ float s_a0;

    // ---- block-coop parameter staging (vectorized) ----
    if (tid < 48) reinterpret_cast<float4*>(s_W0)[tid] =
        reinterpret_cast<const float4*>(W0)[tid];
    reinterpret_cast<float4*>(s_W1)[tid] =
        reinterpret_cast<const float4*>(W1)[tid];
    if (tid < 64) s_ww[tid] = ww[tid];
    if (tid < 16)       s_b0[tid]      = b0[tid];
    else if (tid < 24)  s_b1[tid - 16] = b1[tid - 16];
    else if (tid < 32)  s_bp[tid - 24] = bp[tid - 24];
    else if (tid < 40)  s_cp[tid - 32] = cp[tid - 32];
    else if (tid == 40) s_a0           = a0p[0];

    // ---- per-warp staging: this warp's K group ----
    const float eig = eigen[(size_t)k * Bb + b];   // warp-uniform

    {
        const float2* ewb2 = reinterpret_cast<const float2*>(ew + (size_t)b * 90)
                           + (size_t)k * (Bb * 45);
        float2* sw2 = reinterpret_cast<float2*>(s_w[k]);
        sw2[lane] = ewb2[lane];
        if (lane < 13) sw2[lane + 32] = ewb2[lane + 32];
    }
    {
        const float2* xb2 = reinterpret_cast<const float2*>(x + (size_t)b * 30)
                          + (size_t)k * (Bb * 15);
        if (lane < 15) {
            float2 v = xb2[lane];
            int r0 = 2 * lane, r1 = r0 + 1;
            int j0 = r0 / 3, c0 = r0 % 3;
            int j1 = r1 / 3, c1 = r1 % 3;
            s_x[k][0][j0][c0] = v.x;
            s_x[k][0][j1][c1] = v.y;
            if (c0 == 2) s_pm[k][j0] = fmaxf(v.x, 0.0f);
            if (c1 == 2) s_pm[k][j1] = fmaxf(v.y, 0.0f);
        }
    }
    __syncwarp();

    // ---- degree + dinv (per-warp, lane<10) ----
    if (lane < 10) {
        float d = 0.f;
        #pragma unroll
        for (int i = 0; i < 10; i++)
            if (i != lane) d += s_w[k][eidx(i, lane)];
        s_dinv[k][lane] = (d > 0.f) ? rsqrtf(d) : 0.f;
    }
    __syncwarp();

    // ---- adjacency + R/R_t (per-warp, lane<25, STG.128) ----
    if (lane < 25) {
        const int r = lane * 4;
        float4 vR, vRT;
        #pragma unroll
        for (int t = 0; t < 4; t++) {
            int rr = r + t;
            int n = rr / 10, m = rr % 10;
            bool diag = (n == m);
            float wnm = diag ? 0.f : s_w[k][eidx(n, m)];
            float wmn = diag ? 0.f : s_w[k][eidx(m, n)];
            s_A[k][n][m] = wnm * s_dinv[k][n] * s_dinv[k][m];
            (&vR.x)[t]  = wnm * eig;
            (&vRT.x)[t] = wmn * eig;
        }
        float* dR  = out + OFF_R  + (size_t)k * (Bb * 100) + (size_t)b * 100 + r;
        float* dRT = out + OFF_RT + (size_t)k * (Bb * 100) + (size_t)b * 100 + r;
        *reinterpret_cast<float4*>(dR)  = vR;
        *reinterpret_cast<float4*>(dRT) = vRT;
    }
    __syncwarp();

    // ---- layer-1 hop propagation (per-warp, lane<30: j1, c1) ----
    const int j1 = lane / 3;
    const int c1 = lane - 3 * j1;
    float acol1[10];
    if (lane < 30) {
        #pragma unroll
        for (int i = 0; i < 10; i++) acol1[i] = s_A[k][i][j1];
    }
    #pragma unroll
    for (int hk = 0; hk < 3; hk++) {
        if (lane < 30) {
            const float* src = &s_x[k][hk][0][c1];
            float s = 0.f;
            #pragma unroll
            for (int i = 0; i < 10; i++) s = fmaf(acol1[i], src[i * 4], s);
            s_x[k][hk + 1][j1][c1] = s;
        }
        __syncwarp();
    }

    // barrier 1: cross-warp from here
    __syncthreads();

    // ---- packed 80-thread mapping: (k2, j2, h2) ----
    const int k2 = tid / 20;
    const int r2 = tid % 20;
    const int j2 = r2 >> 1;
    const int h2 = r2 & 1;
    const bool act = (tid < 80);

    // ================= layer-1 projection =================
    if (act) {
        const float4* W0q = reinterpret_cast<const float4*>(s_W0);
        float4 acc0 = make_float4(0.f, 0.f, 0.f, 0.f);
        float4 acc1 = make_float4(0.f, 0.f, 0.f, 0.f);
        #pragma unroll
        for (int hop = 0; hop < 4; hop++) {
            float4 xv = *reinterpret_cast<const float4*>(s_x[k2][hop][j2]);
            int base = hop * 12 + h2 * 2;
            acc0 = f4fma(xv.x, W0q[base + 0], acc0);
            acc1 = f4fma(xv.x, W0q[base + 1], acc1);
            acc0 = f4fma(xv.y, W0q[base + 4], acc0);
            acc1 = f4fma(xv.y, W0q[base + 5], acc1);
            acc0 = f4fma(xv.z, W0q[base + 8], acc0);
            acc1 = f4fma(xv.z, W0q[base + 9], acc1);
        }
        float4 bb0 = reinterpret_cast<const float4*>(s_b0)[h2 * 2];
        float4 bb1 = reinterpret_cast<const float4*>(s_b0)[h2 * 2 + 1];
        float4 v0 = make_float4(lrelu(acc0.x + bb0.x), lrelu(acc0.y + bb0.y),
                                lrelu(acc0.z + bb0.z), lrelu(acc0.w + bb0.w));
        float4 v1 = make_float4(lrelu(acc1.x + bb1.x), lrelu(acc1.y + bb1.y),
                                lrelu(acc1.z + bb1.z), lrelu(acc1.w + bb1.w));
        float* yr = &s_Y1[k2][j2][h2 * 8];
        reinterpret_cast<float4*>(yr)[0] = v0;
        reinterpret_cast<float4*>(yr)[1] = v1;
    }
    __syncwarp();

    // ================= layer-2, Horner form (packed) =================
    const float4* W1q = reinterpret_cast<const float4*>(s_W1);
    float acol2[10];
    float4 y0, y1, y2, y3;
    if (act) {
        #pragma unroll
        for (int i = 0; i < 10; i++) acol2[i] = s_A[k2][i][j2];
        const float4* yq = reinterpret_cast<const float4*>(s_Y1[k2][j2]);
        y0 = yq[0]; y1 = yq[1]; y2 = yq[2]; y3 = yq[3];
        float4 acc = make_float4(0.f, 0.f, 0.f, 0.f);
        acc = proj16(W1q, 3 * 32 + h2, y0, y1, y2, y3, acc);
        *reinterpret_cast<float4*>(&s_z[0][k2][j2][h2 * 4]) = acc;
    }
    __syncthreads();   // barrier 2

    int cur = 0;
    #pragma unroll
    for (int hop = 2; hop >= 1; hop--) {
        if (act) {
            float4 agg = make_float4(0.f, 0.f, 0.f, 0.f);
            const float* zp = &s_z[cur][k2][0][h2 * 4];
            #pragma unroll
            for (int i = 0; i < 10; i++) {
                float4 zv = *reinterpret_cast<const float4*>(&zp[i * 12]);
                agg = f4fma(acol2[i], zv, agg);
            }
            agg = proj16(W1q, hop * 32 + h2, y0, y1, y2, y3, agg);
            *reinterpret_cast<float4*>(&s_z[cur ^ 1][k2][j2][h2 * 4]) = agg;
        }
        __syncthreads();   // barriers 3,4
        cur ^= 1;
    }
    if (act) {
        float4 agg = make_float4(0.f, 0.f, 0.f, 0.f);
        const float* zp = &s_z[cur][k2][0][h2 * 4];
        #pragma unroll
        for (int i = 0; i < 10; i++) {
            float4 zv = *reinterpret_cast<const float4*>(&zp[i * 12]);
            agg = f4fma(acol2[i], zv, agg);
        }
        agg = proj16(W1q, 0 * 32 + h2, y0, y1, y2, y3, agg);
        float4 bb = reinterpret_cast<const float4*>(s_b1)[h2];
        float4 v = make_float4(lrelu(agg.x + bb.x), lrelu(agg.y + bb.y),
                               lrelu(agg.z + bb.z), lrelu(agg.w + bb.w));
        reinterpret_cast<float4*>(s_y[k2][j2])[h2] = v;
    }
    __syncthreads();   // barrier 5

    // ================= epilogue: yw, a_ik, t_k =================
    if (act) {
        const float4* yv = reinterpret_cast<const float4*>(s_y[k2][j2]);
        float4 ya = yv[0], yb = yv[1];
        const float4* wwv = reinterpret_cast<const float4*>(s_ww);
        int d = h2 * 4;
        float4 r;
        r.x = dot4(ya, wwv[(d + 0) * 2]) + dot4(yb, wwv[(d + 0) * 2 + 1]);
        r.y = dot4(ya, wwv[(d + 1) * 2]) + dot4(yb, wwv[(d + 1) * 2 + 1]);
        r.z = dot4(ya, wwv[(d + 2) * 2]) + dot4(yb, wwv[(d + 2) * 2 + 1]);
        r.w = dot4(ya, wwv[(d + 3) * 2]) + dot4(yb, wwv[(d + 3) * 2 + 1]);
        reinterpret_cast<float4*>(s_yw[k2][j2])[h2] = r;
    }
    if (tid < 40) {
        int kk = tid / 10, j = tid % 10;
        const float4* yv = reinterpret_cast<const float4*>(s_y[kk][j]);
        float4 ya = yv[0], yb = yv[1];
        const float4* bpv = reinterpret_cast<const float4*>(s_bp);
        const float4* cpv = reinterpret_cast<const float4*>(s_cp);
        float ay = dot4(ya, bpv[0]) + dot4(yb, bpv[1]);
        float ty = dot4(ya, cpv[0]) + dot4(yb, cpv[1]);
        out[OFF_AIK + (size_t)kk * (Bb * 10) + (size_t)b * 10 + j] = s_a0 + fmaxf(ay, 0.f);
        float tk = ty * (1.0f - s_pm[kk][j]);
        if (tk == 0.0f) tk = -10000000000.0f;
        s_tk[kk][j] = tk;
    }
    __syncthreads();   // barrier 6

    // ===== K_y compute (warps 0-1, broadcast-structured) + t_j (warp 3) =====
    if (tid < 64) {
        const int kk = tid >> 4;
        const int m  = tid & 15;
        if (m < 10) {
            // register-cache y[kk][m] once
            const float4* cv = reinterpret_cast<const float4*>(s_y[kk][m]);
            float4 ym0 = cv[0], ym1 = cv[1];
            #pragma unroll
            for (int n = 0; n < 10; n++) {
                const float4* av = reinterpret_cast<const float4*>(s_yw[kk][n]); // broadcast
                s_K[kk][n][m] = dot4(av[0], ym0) + dot4(av[1], ym1);
            }
        }
    } else if (tid >= 96 && tid < 106) {
        // t_j = softmax over K (overlapped on warp 3)
        int j = tid - 96;
        float t0 = s_tk[0][j], t1 = s_tk[1][j], t2 = s_tk[2][j], t3 = s_tk[3][j];
        float m = fmaxf(fmaxf(t0, t1), fmaxf(t2, t3));
        float e0 = __expf(t0 - m), e1 = __expf(t1 - m);
        float e2 = __expf(t2 - m), e3 = __expf(t3 - m);
        float inv = 1.f / (e0 + e1 + e2 + e3);
        float* pt = out + OFF_TJ + (size_t)b * 10 + j;
        pt[0]            = e0 * inv;
        pt[Bb * 10]      = e1 * inv;
        pt[2 * Bb * 10]  = e2 * inv;
        pt[3 * Bb * 10]  = e3 * inv;
    }
    __syncthreads();   // barrier 7

    // ===== softmax over K -> k_ij =====
    if (tid < 100) {
        float kv0 = s_K[0][0][tid - (tid / 10) * 10 + 0];  // placeholder avoided below
        int n = tid / 10, m = tid % 10;
        float a0v = s_K[0][n][m];
        float a1v = s_K[1][n][m];
        float a2v = s_K[2][n][m];
        float a3v = s_K[3][n][m];
        (void)kv0;
        float mx = fmaxf(fmaxf(a0v, a1v), fmaxf(a2v, a3v));
        float e0 = __expf(a0v - mx), e1 = __expf(a1v - mx);
        float e2 = __expf(a2v - mx), e3 = __expf(a3v - mx);
        float inv = 1.f / (e0 + e1 + e2 + e3);
        float* pk = out + OFF_KIJ + (size_t)b * 100 + tid;
        pk[0]                      = e0 * inv;
        pk[(size_t)(Bb * 100)]     = e1 * inv;
        pk[(size_t)(2 * Bb) * 100] = e2 * inv;
        pk[(size_t)(3 * Bb) * 100] = e3 * inv;
    }
}

extern "C" void kernel_launch(void* const* d_in, const int* in_sizes, int n_in,
                              void* d_out, int out_size) {
    (void)out_size;
    const float* x  = (const float*)d_in[0];
    const float* ew = (const float*)d_in[2];
    int base = 3;
    if (n_in >= 15 && in_sizes[3] == 1 && in_sizes[4] == 1 && in_sizes[5] == 1) base = 6;
    const float* eigen = (const float*)d_in[base + 0];
    const float* a0    = (const float*)d_in[base + 1];
    const float* W0    = (const float*)d_in[base + 2];
    const float* b0    = (const float*)d_in[base + 3];
    const float* W1    = (const float*)d_in[base + 4];
    const float* b1    = (const float*)d_in[base + 5];
    const float* bp    = (const float*)d_in[base + 6];
    const float* cp    = (const float*)d_in[base + 7];
    const float* ww    = (const float*)d_in[base + 8];

    gnn_kernel<<<Bb, 128>>>(x, ew, eigen, a0, W0, b0, W1, b1, bp, cp, ww, (float*)d_out);
}

// round 11
// speedup vs baseline: 1.2983x; 1.0396x over previous
#include <cuda_runtime.h>

#define Bb 32768

#define OFF_KIJ 0
#define OFF_AIK 13107200
#define OFF_TJ  14417920
#define OFF_R   15728640
#define OFF_RT  28835840

typedef unsigned long long u64_t;

static __device__ __forceinline__ int eidx(int i, int j) {
    return i * 9 + j - (j > i ? 1 : 0);
}
static __device__ __forceinline__ float lrelu(float v) {
    return v >= 0.f ? v : 0.01f * v;
}
static __device__ __forceinline__ u64_t bcast2(float v) {
    u64_t r; asm("mov.b64 %0, {%1, %1};" : "=l"(r) : "f"(v)); return r;
}
static __device__ __forceinline__ void ffma2(u64_t& d, u64_t a, u64_t b) {
    asm("fma.rn.f32x2 %0, %1, %2, %0;" : "+l"(d) : "l"(a), "l"(b));
}
static __device__ __forceinline__ u64_t fmul2(u64_t a, u64_t b) {
    u64_t r; asm("mul.rn.f32x2 %0, %1, %2;" : "=l"(r) : "l"(a), "l"(b)); return r;
}
static __device__ __forceinline__ float2 unpk(u64_t v) {
    float2 f; asm("mov.b64 {%0, %1}, %2;" : "=f"(f.x), "=f"(f.y) : "l"(v)); return f;
}
// packed dot of 8 floats (two ulonglong2 pair-vectors)
static __device__ __forceinline__ float pdot8(ulonglong2 a, ulonglong2 b,
                                              ulonglong2 ya, ulonglong2 yb) {
    u64_t s = fmul2(a.x, ya.x);
    ffma2(s, a.y, ya.y);
    ffma2(s, b.x, yb.x);
    ffma2(s, b.y, yb.y);
    float2 f = unpk(s);
    return f.x + f.y;
}
// acc(2xf32x2) += (16-wide y) dot W1 slab; W2 = ulonglong2 view, base in 16B units
static __device__ __forceinline__ void proj16p(const ulonglong2* __restrict__ W2, int base,
                                               float4 y0, float4 y1, float4 y2, float4 y3,
                                               u64_t& a01, u64_t& a23) {
#define PSTEP(c, val) { ulonglong2 w = W2[base + (c) * 2]; u64_t p = bcast2(val); \
                        ffma2(a01, p, w.x); ffma2(a23, p, w.y); }
    PSTEP(0,  y0.x) PSTEP(1,  y0.y) PSTEP(2,  y0.z) PSTEP(3,  y0.w)
    PSTEP(4,  y1.x) PSTEP(5,  y1.y) PSTEP(6,  y1.z) PSTEP(7,  y1.w)
    PSTEP(8,  y2.x) PSTEP(9,  y2.y) PSTEP(10, y2.z) PSTEP(11, y2.w)
    PSTEP(12, y3.x) PSTEP(13, y3.y) PSTEP(14, y3.z) PSTEP(15, y3.w)
#undef PSTEP
}

__global__ __launch_bounds__(128, 8) void gnn_kernel(
    const float* __restrict__ x,
    const float* __restrict__ ew,
    const float* __restrict__ eigen,
    const float* __restrict__ a0p,
    const float* __restrict__ W0,
    const float* __restrict__ b0,
    const float* __restrict__ W1,
    const float* __restrict__ b1,
    const float* __restrict__ bp,
    const float* __restrict__ cp,
    const float* __restrict__ ww,
    float* __restrict__ out)
{
    const int b    = blockIdx.x;
    const int tid  = threadIdx.x;
    const int k    = tid >> 5;
    const int lane = tid & 31;

    __shared__ __align__(8)  float s_w[4][90];
    __shared__ float s_dinv[4][10];
    __shared__ float s_A[4][10][11];
    __shared__ __align__(16) float s_x[4][4][10][4];
    __shared__ __align__(16) float s_Y1[4][10][20];
    __shared__ __align__(16) float s_z[2][4][10][12];
    __shared__ __align__(16) float s_y[4][10][8];
    __shared__ __align__(16) float s_yw[4][10][8];
    __shared__ float s_K[4][10][10];
    __shared__ float s_pm[4][10];
    __shared__ float s_tk[4][10];
    __shared__ __align__(16) float s_W0[192];
    __shared__ __align__(16) float s_W1[512];
    __shared__ __align__(16) float s_b0[16];
    __shared__ __align__(16) float s_b1[8];
    __shared__ __align__(16) float s_bp[8];
    __shared__ __align__(16) float s_cp[8];
    __shared__ __align__(16) float s_ww[64];
    __shared__ float s_a0;

    // ---- block-coop parameter staging (vectorized) ----
    if (tid < 48) reinterpret_cast<float4*>(s_W0)[tid] =
        reinterpret_cast<const float4*>(W0)[tid];
    reinterpret_cast<float4*>(s_W1)[tid] =
        reinterpret_cast<const float4*>(W1)[tid];
    if (tid < 64) s_ww[tid] = ww[tid];
    if (tid < 16)       s_b0[tid]      = b0[tid];
    else if (tid < 24)  s_b1[tid - 16] = b1[tid - 16];
    else if (tid < 32)  s_bp[tid - 24] = bp[tid - 24];
    else if (tid < 40)  s_cp[tid - 32] = cp[tid - 32];
    else if (tid == 40) s_a0           = a0p[0];

    // ---- per-warp staging: this warp's K group ----
    const float eig = eigen[(size_t)k * Bb + b];

    {
        const float2* ewb2 = reinterpret_cast<const float2*>(ew + (size_t)b * 90)
                           + (size_t)k * (Bb * 45);
        float2* sw2 = reinterpret_cast<float2*>(s_w[k]);
        sw2[lane] = ewb2[lane];
        if (lane < 13) sw2[lane + 32] = ewb2[lane + 32];
    }
    {
        const float2* xb2 = reinterpret_cast<const float2*>(x + (size_t)b * 30)
                          + (size_t)k * (Bb * 15);
        if (lane < 15) {
            float2 v = xb2[lane];
            int r0 = 2 * lane, r1 = r0 + 1;
            int j0 = r0 / 3, c0 = r0 % 3;
            int j1 = r1 / 3, c1 = r1 % 3;
            s_x[k][0][j0][c0] = v.x;
            s_x[k][0][j1][c1] = v.y;
            if (c0 == 2) s_pm[k][j0] = fmaxf(v.x, 0.0f);
            if (c1 == 2) s_pm[k][j1] = fmaxf(v.y, 0.0f);
        }
    }
    __syncwarp();

    // ---- degree + dinv ----
    if (lane < 10) {
        float d = 0.f;
        #pragma unroll
        for (int i = 0; i < 10; i++)
            if (i != lane) d += s_w[k][eidx(i, lane)];
        s_dinv[k][lane] = (d > 0.f) ? rsqrtf(d) : 0.f;
    }
    __syncwarp();

    // ---- adjacency + R/R_t ----
    if (lane < 25) {
        const int r = lane * 4;
        float4 vR, vRT;
        #pragma unroll
        for (int t = 0; t < 4; t++) {
            int rr = r + t;
            int n = rr / 10, m = rr % 10;
            bool diag = (n == m);
            float wnm = diag ? 0.f : s_w[k][eidx(n, m)];
            float wmn = diag ? 0.f : s_w[k][eidx(m, n)];
            s_A[k][n][m] = wnm * s_dinv[k][n] * s_dinv[k][m];
            (&vR.x)[t]  = wnm * eig;
            (&vRT.x)[t] = wmn * eig;
        }
        float* dR  = out + OFF_R  + (size_t)k * (Bb * 100) + (size_t)b * 100 + r;
        float* dRT = out + OFF_RT + (size_t)k * (Bb * 100) + (size_t)b * 100 + r;
        *reinterpret_cast<float4*>(dR)  = vR;
        *reinterpret_cast<float4*>(dRT) = vRT;
    }
    __syncwarp();

    // ---- layer-1 hop propagation ----
    const int j1 = lane / 3;
    const int c1 = lane - 3 * j1;
    float acol1[10];
    if (lane < 30) {
        #pragma unroll
        for (int i = 0; i < 10; i++) acol1[i] = s_A[k][i][j1];
    }
    #pragma unroll
    for (int hk = 0; hk < 3; hk++) {
        if (lane < 30) {
            const float* src = &s_x[k][hk][0][c1];
            float s = 0.f;
            #pragma unroll
            for (int i = 0; i < 10; i++) s = fmaf(acol1[i], src[i * 4], s);
            s_x[k][hk + 1][j1][c1] = s;
        }
        __syncwarp();
    }

    // barrier 1
    __syncthreads();

    // ---- packed 80-thread mapping ----
    const int k2 = tid / 20;
    const int r2 = tid % 20;
    const int j2 = r2 >> 1;
    const int h2 = r2 & 1;
    const bool act = (tid < 80);

    // ================= layer-1 projection (f32x2) =================
    if (act) {
        const ulonglong2* W02 = reinterpret_cast<const ulonglong2*>(s_W0);
        u64_t b01 = 0, b23 = 0, c01 = 0, c23 = 0;   // quad0 / quad1 accumulators
        #pragma unroll
        for (int hop = 0; hop < 4; hop++) {
            float4 xv = *reinterpret_cast<const float4*>(s_x[k2][hop][j2]);
            int base = hop * 12 + h2 * 2;
            u64_t px = bcast2(xv.x), py = bcast2(xv.y), pz = bcast2(xv.z);
            ulonglong2 w0 = W02[base + 0], w1 = W02[base + 1];
            ffma2(b01, px, w0.x); ffma2(b23, px, w0.y);
            ffma2(c01, px, w1.x); ffma2(c23, px, w1.y);
            w0 = W02[base + 4]; w1 = W02[base + 5];
            ffma2(b01, py, w0.x); ffma2(b23, py, w0.y);
            ffma2(c01, py, w1.x); ffma2(c23, py, w1.y);
            w0 = W02[base + 8]; w1 = W02[base + 9];
            ffma2(b01, pz, w0.x); ffma2(b23, pz, w0.y);
            ffma2(c01, pz, w1.x); ffma2(c23, pz, w1.y);
        }
        float2 f0 = unpk(b01), f1 = unpk(b23), f2 = unpk(c01), f3 = unpk(c23);
        float4 bb0 = reinterpret_cast<const float4*>(s_b0)[h2 * 2];
        float4 bb1 = reinterpret_cast<const float4*>(s_b0)[h2 * 2 + 1];
        float4 v0 = make_float4(lrelu(f0.x + bb0.x), lrelu(f0.y + bb0.y),
                                lrelu(f1.x + bb0.z), lrelu(f1.y + bb0.w));
        float4 v1 = make_float4(lrelu(f2.x + bb1.x), lrelu(f2.y + bb1.y),
                                lrelu(f3.x + bb1.z), lrelu(f3.y + bb1.w));
        float* yr = &s_Y1[k2][j2][h2 * 8];
        reinterpret_cast<float4*>(yr)[0] = v0;
        reinterpret_cast<float4*>(yr)[1] = v1;
    }
    __syncwarp();

    // ================= layer-2, Horner form (f32x2) =================
    const ulonglong2* W12 = reinterpret_cast<const ulonglong2*>(s_W1);
    float acol2[10];
    float4 y0, y1, y2, y3;
    if (act) {
        #pragma unroll
        for (int i = 0; i < 10; i++) acol2[i] = s_A[k2][i][j2];
        const float4* yq = reinterpret_cast<const float4*>(s_Y1[k2][j2]);
        y0 = yq[0]; y1 = yq[1]; y2 = yq[2]; y3 = yq[3];
        u64_t a01 = 0, a23 = 0;
        proj16p(W12, 3 * 32 + h2, y0, y1, y2, y3, a01, a23);
        ulonglong2* zd = reinterpret_cast<ulonglong2*>(&s_z[0][k2][j2][h2 * 4]);
        zd->x = a01; zd->y = a23;
    }
    __syncthreads();   // barrier 2

    int cur = 0;
    #pragma unroll
    for (int hop = 2; hop >= 1; hop--) {
        if (act) {
            u64_t g01 = 0, g23 = 0;
            const char* zbase = reinterpret_cast<const char*>(&s_z[cur][k2][0][h2 * 4]);
            #pragma unroll
            for (int i = 0; i < 10; i++) {
                ulonglong2 zv = *reinterpret_cast<const ulonglong2*>(zbase + i * 48);
                u64_t pa = bcast2(acol2[i]);
                ffma2(g01, pa, zv.x);
                ffma2(g23, pa, zv.y);
            }
            proj16p(W12, hop * 32 + h2, y0, y1, y2, y3, g01, g23);
            ulonglong2* zd = reinterpret_cast<ulonglong2*>(&s_z[cur ^ 1][k2][j2][h2 * 4]);
            zd->x = g01; zd->y = g23;
        }
        __syncthreads();   // barriers 3,4
        cur ^= 1;
    }
    if (act) {
        u64_t g01 = 0, g23 = 0;
        const char* zbase = reinterpret_cast<const char*>(&s_z[cur][k2][0][h2 * 4]);
        #pragma unroll
        for (int i = 0; i < 10; i++) {
            ulonglong2 zv = *reinterpret_cast<const ulonglong2*>(zbase + i * 48);
            u64_t pa = bcast2(acol2[i]);
            ffma2(g01, pa, zv.x);
            ffma2(g23, pa, zv.y);
        }
        proj16p(W12, 0 * 32 + h2, y0, y1, y2, y3, g01, g23);
        float2 f0 = unpk(g01), f1 = unpk(g23);
        float4 bb = reinterpret_cast<const float4*>(s_b1)[h2];
        float4 v = make_float4(lrelu(f0.x + bb.x), lrelu(f0.y + bb.y),
                               lrelu(f1.x + bb.z), lrelu(f1.y + bb.w));
        reinterpret_cast<float4*>(s_y[k2][j2])[h2] = v;
    }
    __syncthreads();   // barrier 5

    // ================= epilogue: yw, a_ik, t_k =================
    if (act) {
        const ulonglong2* yv = reinterpret_cast<const ulonglong2*>(s_y[k2][j2]);
        ulonglong2 ya = yv[0], yb = yv[1];
        const ulonglong2* wwv = reinterpret_cast<const ulonglong2*>(s_ww);
        int d = h2 * 4;
        float4 r;
        r.x = pdot8(wwv[(d + 0) * 2], wwv[(d + 0) * 2 + 1], ya, yb);
        r.y = pdot8(wwv[(d + 1) * 2], wwv[(d + 1) * 2 + 1], ya, yb);
        r.z = pdot8(wwv[(d + 2) * 2], wwv[(d + 2) * 2 + 1], ya, yb);
        r.w = pdot8(wwv[(d + 3) * 2], wwv[(d + 3) * 2 + 1], ya, yb);
        reinterpret_cast<float4*>(s_yw[k2][j2])[h2] = r;
    }
    if (tid < 40) {
        int kk = tid / 10, j = tid % 10;
        const ulonglong2* yv = reinterpret_cast<const ulonglong2*>(s_y[kk][j]);
        ulonglong2 ya = yv[0], yb = yv[1];
        const ulonglong2* bpv = reinterpret_cast<const ulonglong2*>(s_bp);
        const ulonglong2* cpv = reinterpret_cast<const ulonglong2*>(s_cp);
        float ay = pdot8(ya, yb, bpv[0], bpv[0 + 1]);
        float ty = pdot8(ya, yb, cpv[0], cpv[0 + 1]);
        out[OFF_AIK + (size_t)kk * (Bb * 10) + (size_t)b * 10 + j] = s_a0 + fmaxf(ay, 0.f);
        float tk = ty * (1.0f - s_pm[kk][j]);
        if (tk == 0.0f) tk = -10000000000.0f;
        s_tk[kk][j] = tk;
    }
    __syncthreads();   // barrier 6

    // ===== K_y compute (warps 0-1, broadcast-structured) + t_j (warp 3) =====
    if (tid < 64) {
        const int kk = tid >> 4;
        const int m  = tid & 15;
        if (m < 10) {
            const ulonglong2* cv = reinterpret_cast<const ulonglong2*>(s_y[kk][m]);
            ulonglong2 ym0 = cv[0], ym1 = cv[1];
            #pragma unroll
            for (int n = 0; n < 10; n++) {
                const ulonglong2* av = reinterpret_cast<const ulonglong2*>(s_yw[kk][n]);
                s_K[kk][n][m] = pdot8(av[0], av[1], ym0, ym1);
            }
        }
    } else if (tid >= 96 && tid < 106) {
        int j = tid - 96;
        float t0 = s_tk[0][j], t1 = s_tk[1][j], t2 = s_tk[2][j], t3 = s_tk[3][j];
        float m = fmaxf(fmaxf(t0, t1), fmaxf(t2, t3));
        float e0 = __expf(t0 - m), e1 = __expf(t1 - m);
        float e2 = __expf(t2 - m), e3 = __expf(t3 - m);
        float inv = 1.f / (e0 + e1 + e2 + e3);
        float* pt = out + OFF_TJ + (size_t)b * 10 + j;
        pt[0]            = e0 * inv;
        pt[Bb * 10]      = e1 * inv;
        pt[2 * Bb * 10]  = e2 * inv;
        pt[3 * Bb * 10]  = e3 * inv;
    }
    __syncthreads();   // barrier 7

    // ===== softmax over K -> k_ij =====
    if (tid < 100) {
        int n = tid / 10, m = tid % 10;
        float a0v = s_K[0][n][m];
        float a1v = s_K[1][n][m];
        float a2v = s_K[2][n][m];
        float a3v = s_K[3][n][m];
        float mx = fmaxf(fmaxf(a0v, a1v), fmaxf(a2v, a3v));
        float e0 = __expf(a0v - mx), e1 = __expf(a1v - mx);
        float e2 = __expf(a2v - mx), e3 = __expf(a3v - mx);
        float inv = 1.f / (e0 + e1 + e2 + e3);
        float* pk = out + OFF_KIJ + (size_t)b * 100 + tid;
        pk[0]                      = e0 * inv;
        pk[(size_t)(Bb * 100)]     = e1 * inv;
        pk[(size_t)(2 * Bb) * 100] = e2 * inv;
        pk[(size_t)(3 * Bb) * 100] = e3 * inv;
    }
}

extern "C" void kernel_launch(void* const* d_in, const int* in_sizes, int n_in,
                              void* d_out, int out_size) {
    (void)out_size;
    const float* x  = (const float*)d_in[0];
    const float* ew = (const float*)d_in[2];
    int base = 3;
    if (n_in >= 15 && in_sizes[3] == 1 && in_sizes[4] == 1 && in_sizes[5] == 1) base = 6;
    const float* eigen = (const float*)d_in[base + 0];
    const float* a0    = (const float*)d_in[base + 1];
    const float* W0    = (const float*)d_in[base + 2];
    const float* b0    = (const float*)d_in[base + 3];
    const float* W1    = (const float*)d_in[base + 4];
    const float* b1    = (const float*)d_in[base + 5];
    const float* bp    = (const float*)d_in[base + 6];
    const float* cp    = (const float*)d_in[base + 7];
    const float* ww    = (const float*)d_in[base + 8];

    gnn_kernel<<<Bb, 128>>>(x, ew, eigen, a0, W0, b0, W1, b1, bp, cp, ww, (float*)d_out);
}